// round 10
// baseline (speedup 1.0000x reference)
#include <cuda_runtime.h>
#include <cstdint>

#define N_NODES 65536
#define N_EDGES 524288
#define NGRAPH  64

// ---------------- device scratch (zero-initialized at module load) ----------------
__device__ int   g_count[N_NODES];
__device__ int   g_fill[N_NODES];
__device__ int   g_rowptr[N_NODES + 1];
__device__ int   g_ssrc[N_EDGES];
__device__ __align__(16) float g_scoef[(size_t)N_EDGES * 12];
__device__ __align__(16) float g_cat0[(size_t)N_NODES * 128];      // [h3 | h2]
__device__ __align__(16) float g_cat1[(size_t)N_NODES * 96];       // [h4 | h1]
__device__ __align__(16) float g_h5[(size_t)N_NODES * 32];
__device__ __align__(16) float g_part[(size_t)256 * NGRAPH * 128];

// ---------------- packed f32x2 FMA (sm_103a FFMA2) ----------------
__device__ __forceinline__ float2 ffma2(float2 a, float2 b, float2 c) {
    float2 d;
    asm("fma.rn.f32x2 %0, %1, %2, %3;"
        : "=l"(*reinterpret_cast<unsigned long long*>(&d))
        : "l"(*reinterpret_cast<unsigned long long*>(&a)),
          "l"(*reinterpret_cast<unsigned long long*>(&b)),
          "l"(*reinterpret_cast<unsigned long long*>(&c)));
    return d;
}

// ---------------- CSR build ----------------
// NOTE: no zero_kernel. g_count/g_fill start zero (static init) and are re-zeroed
// by spline enc0 (LAYER 0) each run, which executes after fill_kernel in stream order.

__global__ void count_kernel(const int* __restrict__ ei) {
    int e = blockIdx.x * blockDim.x + threadIdx.x;
    if (e < N_EDGES) {
        int dst = ei[N_EDGES + e];
        if ((unsigned)dst < (unsigned)N_NODES) atomicAdd(&g_count[dst], 1);
    }
}

__global__ void scan_kernel() {
    __shared__ int ssum[1024];
    int t = threadIdx.x;
    int base = t * 64;
    int sum = 0;
    for (int j = 0; j < 64; ++j) sum += g_count[base + j];
    ssum[t] = sum;
    __syncthreads();
    for (int off = 1; off < 1024; off <<= 1) {
        int v = (t >= off) ? ssum[t - off] : 0;
        __syncthreads();
        ssum[t] += v;
        __syncthreads();
    }
    int run = ssum[t] - sum;
    for (int j = 0; j < 64; ++j) { g_rowptr[base + j] = run; run += g_count[base + j]; }
    if (t == 1023) g_rowptr[N_NODES] = run;
}

__global__ void fill_kernel(const int* __restrict__ ei, const float* __restrict__ pos) {
    int e = blockIdx.x * blockDim.x + threadIdx.x;
    if (e >= N_EDGES) return;
    int src = ei[e];
    int dst = ei[N_EDGES + e];
    if ((unsigned)src >= (unsigned)N_NODES || (unsigned)dst >= (unsigned)N_NODES) return;
    float p0 = pos[2 * e], p1 = pos[2 * e + 1];
    int   b0i = (int)floorf(p0);
    int   b1i = (int)floorf(p1);
    float f0 = p0 - (float)b0i;
    float f1 = p1 - (float)b1i;
    float ba[3] = {0.5f * (1.f - f0) * (1.f - f0), -f0 * f0 + f0 + 0.5f, 0.5f * f0 * f0};
    float bb[3] = {0.5f * (1.f - f1) * (1.f - f1), -f1 * f1 + f1 + 0.5f, 0.5f * f1 * f1};
    int ia[3], ib[3];
#pragma unroll
    for (int t = 0; t < 3; ++t) {
        ia[t] = min(max(b0i + t, 0), 2);
        ib[t] = min(max(b1i + t, 0), 2);
    }
    float ck[9];
#pragma unroll
    for (int k = 0; k < 9; ++k) ck[k] = 0.f;
#pragma unroll
    for (int i = 0; i < 3; ++i)
#pragma unroll
        for (int j = 0; j < 3; ++j)
            ck[ia[i] + 3 * ib[j]] += ba[i] * bb[j];

    int slot = g_rowptr[dst] + atomicAdd(&g_fill[dst], 1);
    g_ssrc[slot] = src;
    float* cw = g_scoef + (size_t)slot * 12;
#pragma unroll
    for (int k = 0; k < 9; ++k) cw[k] = ck[k];
    cw[9] = 0.f; cw[10] = 0.f; cw[11] = 0.f;
}

// ---------------- fused SplineConv layer (8 nodes/block, warp-split-K GEMM) ----------------
template <int CI, int CO, int LAYER>
__launch_bounds__(256)
__global__ void spline_conv_kernel(const float* __restrict__ xext,
                                   const float* __restrict__ W,     // [9*CI][CO]
                                   const float* __restrict__ root,  // [CI][CO]
                                   const float* __restrict__ bias)  // [CO]
{
    constexpr int KT  = 9 * CI;
    constexpr int CPL = (CI + 31) / 32;
    constexpr int SMAX = (8 * KT > 64 * CO) ? 8 * KT : 64 * CO;   // Ys / reduction overlay

    const float* xin; float* xout; int istride, ostride;
    if constexpr (LAYER == 0)      { xin = xext;        istride = 16;  xout = g_cat1 + 64; ostride = 96;  }
    else if constexpr (LAYER == 1) { xin = g_cat1 + 64; istride = 96;  xout = g_cat0 + 64; ostride = 128; }
    else if constexpr (LAYER == 2) { xin = g_cat0 + 64; istride = 128; xout = g_cat0;      ostride = 128; }
    else if constexpr (LAYER == 3) { xin = g_cat0;      istride = 128; xout = g_cat1;      ostride = 96;  }
    else                           { xin = g_cat1;      istride = 96;  xout = g_h5;        ostride = 32;  }

    __shared__ __align__(16) float smem[SMAX + 8 * CI];
    float* Ys = smem;             // [8][KT]  (later overlaid by reduction buffer)
    float* Xs = smem + SMAX;      // [8][CI]

    int tid = threadIdx.x, lane = tid & 31, warp = tid >> 5;
    int nbase = blockIdx.x * 8;

    // Re-zero CSR scratch for the next run (g_count/g_fill are dead after fill_kernel).
    if constexpr (LAYER == 0) {
        if (tid < 8) { g_count[nbase + tid] = 0; g_fill[nbase + tid] = 0; }
    }

    // ---- phase 1: warp per node, depth-2 edge pipeline ----
    {
        int n = nbase + warp;
        int s0 = g_rowptr[n], s1 = g_rowptr[n + 1];
        float acc[9][CPL];
#pragma unroll
        for (int k = 0; k < 9; ++k)
#pragma unroll
            for (int r = 0; r < CPL; ++r) acc[k][r] = 0.f;

        float4 cbuf[2][3];
        float  xbuf[2][CPL];
        auto LOAD = [&](int s, int b) {
            int src = g_ssrc[s];
            const float4* cp = reinterpret_cast<const float4*>(g_scoef + (size_t)s * 12);
            cbuf[b][0] = cp[0]; cbuf[b][1] = cp[1]; cbuf[b][2] = cp[2];
#pragma unroll
            for (int r = 0; r < CPL; ++r) {
                int c = lane + 32 * r;
                xbuf[b][r] = (c < CI) ? __ldg(xin + (size_t)src * istride + c) : 0.f;
            }
        };
        if (s0 < s1) LOAD(s0, 0);
        if (s0 + 1 < s1) LOAD(s0 + 1, 1);
        for (int s = s0; s < s1; ++s) {
            int b = (s - s0) & 1;
            float c9[9] = {cbuf[b][0].x, cbuf[b][0].y, cbuf[b][0].z, cbuf[b][0].w,
                           cbuf[b][1].x, cbuf[b][1].y, cbuf[b][1].z, cbuf[b][1].w,
                           cbuf[b][2].x};
            float xv[CPL];
#pragma unroll
            for (int r = 0; r < CPL; ++r) xv[r] = xbuf[b][r];
            if (s + 2 < s1) LOAD(s + 2, b);
#pragma unroll
            for (int k = 0; k < 9; ++k)
#pragma unroll
                for (int r = 0; r < CPL; ++r) acc[k][r] += c9[k] * xv[r];
        }
        float inv = 1.0f / (float)max(1, s1 - s0);
#pragma unroll
        for (int r = 0; r < CPL; ++r) {
            int c = lane + 32 * r;
            if (c < CI) {
#pragma unroll
                for (int k = 0; k < 9; ++k) Ys[warp * KT + k * CI + c] = acc[k][r] * inv;
                Xs[warp * CI + c] = __ldg(xin + (size_t)n * istride + c);
            }
        }
    }
    __syncthreads();

    // ---- phase 2: warp-split-K GEMM, broadcast y, float2 weights, packed FFMA2 ----
    if constexpr (CO == 64) {
        // lane owns column pair (2*lane, 2*lane+1)
        float2 acc2[8];
#pragma unroll
        for (int r = 0; r < 8; ++r) acc2[r] = make_float2(0.f, 0.f);

#pragma unroll 4
        for (int p4 = warp; p4 < KT / 4; p4 += 8) {
            int k = 4 * p4;
            float2 w0 = *reinterpret_cast<const float2*>(W + (size_t)(k + 0) * CO + 2 * lane);
            float2 w1 = *reinterpret_cast<const float2*>(W + (size_t)(k + 1) * CO + 2 * lane);
            float2 w2 = *reinterpret_cast<const float2*>(W + (size_t)(k + 2) * CO + 2 * lane);
            float2 w3 = *reinterpret_cast<const float2*>(W + (size_t)(k + 3) * CO + 2 * lane);
#pragma unroll
            for (int r = 0; r < 8; ++r) {
                float4 y = *reinterpret_cast<const float4*>(&Ys[r * KT + k]);
                acc2[r] = ffma2(make_float2(y.x, y.x), w0, acc2[r]);
                acc2[r] = ffma2(make_float2(y.y, y.y), w1, acc2[r]);
                acc2[r] = ffma2(make_float2(y.z, y.z), w2, acc2[r]);
                acc2[r] = ffma2(make_float2(y.w, y.w), w3, acc2[r]);
            }
        }
#pragma unroll 4
        for (int p4 = warp; p4 < CI / 4; p4 += 8) {
            int k = 4 * p4;
            float2 w0 = *reinterpret_cast<const float2*>(root + (size_t)(k + 0) * CO + 2 * lane);
            float2 w1 = *reinterpret_cast<const float2*>(root + (size_t)(k + 1) * CO + 2 * lane);
            float2 w2 = *reinterpret_cast<const float2*>(root + (size_t)(k + 2) * CO + 2 * lane);
            float2 w3 = *reinterpret_cast<const float2*>(root + (size_t)(k + 3) * CO + 2 * lane);
#pragma unroll
            for (int r = 0; r < 8; ++r) {
                float4 y = *reinterpret_cast<const float4*>(&Xs[r * CI + k]);
                acc2[r] = ffma2(make_float2(y.x, y.x), w0, acc2[r]);
                acc2[r] = ffma2(make_float2(y.y, y.y), w1, acc2[r]);
                acc2[r] = ffma2(make_float2(y.z, y.z), w2, acc2[r]);
                acc2[r] = ffma2(make_float2(y.w, y.w), w3, acc2[r]);
            }
        }
        __syncthreads();
        float2* red2 = reinterpret_cast<float2*>(smem);   // [8 warps][8 rows][32 lane-pairs]
#pragma unroll
        for (int r = 0; r < 8; ++r) red2[(warp * 8 + r) * 32 + lane] = acc2[r];
        __syncthreads();
        int r = warp;   // 8 warps x 32 lanes = 8 rows x 32 col-pairs
        float2 v = *reinterpret_cast<const float2*>(bias + 2 * lane);
#pragma unroll
        for (int w = 0; w < 8; ++w) {
            float2 t = red2[(w * 8 + r) * 32 + lane];
            v.x += t.x; v.y += t.y;
        }
        v.x = fminf(fmaxf(v.x, 0.f), 6.f);
        v.y = fminf(fmaxf(v.y, 0.f), 6.f);
        *reinterpret_cast<float2*>(xout + (size_t)(nbase + r) * ostride + 2 * lane) = v;
    } else {  // CO == 32: lane owns one column, rows packed in pairs
        float2 acc2[4];
#pragma unroll
        for (int j = 0; j < 4; ++j) acc2[j] = make_float2(0.f, 0.f);

#pragma unroll 4
        for (int p4 = warp; p4 < KT / 4; p4 += 8) {
            int k = 4 * p4;
            float w4[4];
#pragma unroll
            for (int i = 0; i < 4; ++i) w4[i] = __ldg(W + (size_t)(k + i) * CO + lane);
#pragma unroll
            for (int j = 0; j < 4; ++j) {
                float4 ya = *reinterpret_cast<const float4*>(&Ys[(2 * j) * KT + k]);
                float4 yb = *reinterpret_cast<const float4*>(&Ys[(2 * j + 1) * KT + k]);
                acc2[j] = ffma2(make_float2(ya.x, yb.x), make_float2(w4[0], w4[0]), acc2[j]);
                acc2[j] = ffma2(make_float2(ya.y, yb.y), make_float2(w4[1], w4[1]), acc2[j]);
                acc2[j] = ffma2(make_float2(ya.z, yb.z), make_float2(w4[2], w4[2]), acc2[j]);
                acc2[j] = ffma2(make_float2(ya.w, yb.w), make_float2(w4[3], w4[3]), acc2[j]);
            }
        }
#pragma unroll 4
        for (int p4 = warp; p4 < CI / 4; p4 += 8) {
            int k = 4 * p4;
            float w4[4];
#pragma unroll
            for (int i = 0; i < 4; ++i) w4[i] = __ldg(root + (size_t)(k + i) * CO + lane);
#pragma unroll
            for (int j = 0; j < 4; ++j) {
                float4 ya = *reinterpret_cast<const float4*>(&Xs[(2 * j) * CI + k]);
                float4 yb = *reinterpret_cast<const float4*>(&Xs[(2 * j + 1) * CI + k]);
                acc2[j] = ffma2(make_float2(ya.x, yb.x), make_float2(w4[0], w4[0]), acc2[j]);
                acc2[j] = ffma2(make_float2(ya.y, yb.y), make_float2(w4[1], w4[1]), acc2[j]);
                acc2[j] = ffma2(make_float2(ya.z, yb.z), make_float2(w4[2], w4[2]), acc2[j]);
                acc2[j] = ffma2(make_float2(ya.w, yb.w), make_float2(w4[3], w4[3]), acc2[j]);
            }
        }
        __syncthreads();
        float* red = smem;   // [8 warps][8 rows][CO]
#pragma unroll
        for (int j = 0; j < 4; ++j) {
            red[(warp * 8 + 2 * j) * CO + lane]     = acc2[j].x;
            red[(warp * 8 + 2 * j + 1) * CO + lane] = acc2[j].y;
        }
        __syncthreads();
        int r = warp;
        float v = __ldg(bias + lane);
#pragma unroll
        for (int w = 0; w < 8; ++w) v += red[(w * 8 + r) * CO + lane];
        v = fminf(fmaxf(v, 0.f), 6.f);
        xout[(size_t)(nbase + r) * ostride + lane] = v;
    }
}

// ---------------- lin1 split-K GEMM: [64,32768] x [32768,128] ----------------
__launch_bounds__(256)
__global__ void lin1_partial_kernel(const float* __restrict__ W) {
    __shared__ __align__(16) float As[64 * 32];
    __shared__ __align__(16) float Bs[32 * 128];
    int tid = threadIdx.x;
    int k0 = blockIdx.x * 128;
    int colg = tid & 31;
    int rowg = tid >> 5;
    float4 acc[8];
#pragma unroll
    for (int i = 0; i < 8; ++i) acc[i] = make_float4(0.f, 0.f, 0.f, 0.f);

    for (int ch = 0; ch < 4; ++ch) {
        int kb = k0 + ch * 32;
        for (int idx = tid; idx < 64 * 32; idx += 256) {
            int b = idx >> 5, kk = idx & 31;
            As[idx] = g_h5[(size_t)b * 32768 + kb + kk];
        }
        for (int idx = tid; idx < 32 * 128; idx += 256) {
            int kk = idx >> 7, c = idx & 127;
            Bs[idx] = W[(size_t)(kb + kk) * 128 + c];
        }
        __syncthreads();
        for (int kk = 0; kk < 32; ++kk) {
            float4 w = *reinterpret_cast<const float4*>(&Bs[kk * 128 + 4 * colg]);
#pragma unroll
            for (int i = 0; i < 8; ++i) {
                float a = As[(rowg + 8 * i) * 32 + kk];
                acc[i].x += a * w.x; acc[i].y += a * w.y;
                acc[i].z += a * w.z; acc[i].w += a * w.w;
            }
        }
        __syncthreads();
    }
#pragma unroll
    for (int i = 0; i < 8; ++i)
        *reinterpret_cast<float4*>(&g_part[(size_t)blockIdx.x * 8192 + (rowg + 8 * i) * 128 + 4 * colg]) = acc[i];
}

__global__ void lin2_kernel(const float* __restrict__ lin1b,
                            const float* __restrict__ lin2W, const float* __restrict__ lin2b,
                            float* __restrict__ out) {
    __shared__ float h[128];
    int b = blockIdx.x, c = threadIdx.x;
    float s = 0.f;
    for (int sp = 0; sp < 256; ++sp) s += g_part[(size_t)sp * 8192 + b * 128 + c];
    s += lin1b[c];
    h[c] = fmaxf(s, 0.f);
    __syncthreads();
    if (c < 3) {
        float o = lin2b[c];
#pragma unroll 4
        for (int i = 0; i < 128; ++i) o += h[i] * lin2W[i * 3 + c];
        out[b * 3 + c] = o;
    }
}

// ---------------- host ----------------
extern "C" void kernel_launch(void* const* d_in, const int* in_sizes, int n_in,
                              void* d_out, int out_size) {
    const float* x    = (const float*)d_in[0];
    const int*   ei   = (const int*)d_in[1];     // int32 (JAX x64 disabled)
    const float* pos  = (const float*)d_in[2];
    const float* enc0_W = (const float*)d_in[4],  *enc0_R = (const float*)d_in[5],  *enc0_b = (const float*)d_in[6];
    const float* enc1_W = (const float*)d_in[7],  *enc1_R = (const float*)d_in[8],  *enc1_b = (const float*)d_in[9];
    const float* enc2_W = (const float*)d_in[10], *enc2_R = (const float*)d_in[11], *enc2_b = (const float*)d_in[12];
    const float* dec0_W = (const float*)d_in[13], *dec0_R = (const float*)d_in[14], *dec0_b = (const float*)d_in[15];
    const float* dec1_W = (const float*)d_in[16], *dec1_R = (const float*)d_in[17], *dec1_b = (const float*)d_in[18];
    const float* lin1_W = (const float*)d_in[19], *lin1_b = (const float*)d_in[20];
    const float* lin2_W = (const float*)d_in[21], *lin2_b = (const float*)d_in[22];
    float* out = (float*)d_out;

    // CSR build (g_count/g_fill zeroed at load / by previous run's enc0)
    count_kernel<<<(N_EDGES + 255) / 256, 256>>>(ei);
    scan_kernel<<<1, 1024>>>();
    fill_kernel<<<(N_EDGES + 255) / 256, 256>>>(ei, pos);

    spline_conv_kernel<16, 32, 0><<<N_NODES / 8, 256>>>(x, enc0_W, enc0_R, enc0_b);
    spline_conv_kernel<32, 64, 1><<<N_NODES / 8, 256>>>(nullptr, enc1_W, enc1_R, enc1_b);
    spline_conv_kernel<64, 64, 2><<<N_NODES / 8, 256>>>(nullptr, enc2_W, enc2_R, enc2_b);
    spline_conv_kernel<128, 64, 3><<<N_NODES / 8, 256>>>(nullptr, dec0_W, dec0_R, dec0_b);
    spline_conv_kernel<96, 32, 4><<<N_NODES / 8, 256>>>(nullptr, dec1_W, dec1_R, dec1_b);

    lin1_partial_kernel<<<256, 256>>>(lin1_W);
    lin2_kernel<<<NGRAPH, 128>>>(lin1_b, lin2_W, lin2_b, out);
}

// round 13
// speedup vs baseline: 1.1087x; 1.1087x over previous
#include <cuda_runtime.h>
#include <cstdint>

#define N_NODES 65536
#define N_EDGES 524288
#define NGRAPH  64

// ---------------- device scratch (zero-initialized at module load) ----------------
__device__ int   g_count[N_NODES];
__device__ int   g_fill[N_NODES];
__device__ int   g_rowptr[N_NODES + 1];
__device__ int   g_ssrc[N_EDGES];
__device__ __align__(16) float g_scoef[(size_t)N_EDGES * 12];
__device__ __align__(16) float g_cat0[(size_t)N_NODES * 128];      // [h3 | h2]
__device__ __align__(16) float g_cat1[(size_t)N_NODES * 96];       // [h4 | h1]
__device__ __align__(16) float g_h5[(size_t)N_NODES * 32];
__device__ __align__(16) float g_part[(size_t)256 * NGRAPH * 128];

// ---------------- packed f32x2 FMA (sm_103a FFMA2) ----------------
__device__ __forceinline__ float2 ffma2(float2 a, float2 b, float2 c) {
    float2 d;
    asm("fma.rn.f32x2 %0, %1, %2, %3;"
        : "=l"(*reinterpret_cast<unsigned long long*>(&d))
        : "l"(*reinterpret_cast<unsigned long long*>(&a)),
          "l"(*reinterpret_cast<unsigned long long*>(&b)),
          "l"(*reinterpret_cast<unsigned long long*>(&c)));
    return d;
}

// ---------------- CSR build ----------------
__global__ void count_kernel(const int* __restrict__ ei) {
    int e = blockIdx.x * blockDim.x + threadIdx.x;
    if (e < N_EDGES) {
        int dst = ei[N_EDGES + e];
        if ((unsigned)dst < (unsigned)N_NODES) atomicAdd(&g_count[dst], 1);
    }
}

__global__ void scan_kernel() {
    __shared__ int ssum[1024];
    int t = threadIdx.x;
    int base = t * 64;
    int sum = 0;
    for (int j = 0; j < 64; ++j) sum += g_count[base + j];
    ssum[t] = sum;
    __syncthreads();
    for (int off = 1; off < 1024; off <<= 1) {
        int v = (t >= off) ? ssum[t - off] : 0;
        __syncthreads();
        ssum[t] += v;
        __syncthreads();
    }
    int run = ssum[t] - sum;
    for (int j = 0; j < 64; ++j) { g_rowptr[base + j] = run; run += g_count[base + j]; }
    if (t == 1023) g_rowptr[N_NODES] = run;
}

__global__ void fill_kernel(const int* __restrict__ ei, const float* __restrict__ pos) {
    int e = blockIdx.x * blockDim.x + threadIdx.x;
    if (e >= N_EDGES) return;
    int src = ei[e];
    int dst = ei[N_EDGES + e];
    if ((unsigned)src >= (unsigned)N_NODES || (unsigned)dst >= (unsigned)N_NODES) return;
    float p0 = pos[2 * e], p1 = pos[2 * e + 1];
    int   b0i = (int)floorf(p0);
    int   b1i = (int)floorf(p1);
    float f0 = p0 - (float)b0i;
    float f1 = p1 - (float)b1i;
    float ba[3] = {0.5f * (1.f - f0) * (1.f - f0), -f0 * f0 + f0 + 0.5f, 0.5f * f0 * f0};
    float bb[3] = {0.5f * (1.f - f1) * (1.f - f1), -f1 * f1 + f1 + 0.5f, 0.5f * f1 * f1};
    int ia[3], ib[3];
#pragma unroll
    for (int t = 0; t < 3; ++t) {
        ia[t] = min(max(b0i + t, 0), 2);
        ib[t] = min(max(b1i + t, 0), 2);
    }
    float ck[9];
#pragma unroll
    for (int k = 0; k < 9; ++k) ck[k] = 0.f;
#pragma unroll
    for (int i = 0; i < 3; ++i)
#pragma unroll
        for (int j = 0; j < 3; ++j)
            ck[ia[i] + 3 * ib[j]] += ba[i] * bb[j];

    int slot = g_rowptr[dst] + atomicAdd(&g_fill[dst], 1);
    g_ssrc[slot] = src;
    float* cw = g_scoef + (size_t)slot * 12;
#pragma unroll
    for (int k = 0; k < 9; ++k) cw[k] = ck[k];
    cw[9] = 0.f; cw[10] = 0.f; cw[11] = 0.f;
}

// ---------------- fused SplineConv layer ----------------
// Phase 1: warp per node, EPW edges processed concurrently by lane-groups of LPE lanes,
//          float4 gathers, shfl_xor cross-group reduction.
// Phase 2: warp-split-K GEMM (broadcast smem y, global-stream weights, packed FFMA2).
template <int CI, int CO, int LAYER>
__launch_bounds__(256)
__global__ void spline_conv_kernel(const float* __restrict__ xext,
                                   const float* __restrict__ W,     // [9*CI][CO]
                                   const float* __restrict__ root,  // [CI][CO]
                                   const float* __restrict__ bias)  // [CO]
{
    constexpr int KT  = 9 * CI;
    constexpr int LPE = (CI >= 128) ? 32 : CI / 4;   // lanes per edge: 4,8,16,24,32
    constexpr int EPW = 32 / LPE;                    // edges per warp-iter: 8,4,2,1,1
    constexpr int SMAX = (8 * KT > 64 * CO) ? 8 * KT : 64 * CO;

    const float* xin; float* xout; int istride, ostride;
    if constexpr (LAYER == 0)      { xin = xext;        istride = 16;  xout = g_cat1 + 64; ostride = 96;  }
    else if constexpr (LAYER == 1) { xin = g_cat1 + 64; istride = 96;  xout = g_cat0 + 64; ostride = 128; }
    else if constexpr (LAYER == 2) { xin = g_cat0 + 64; istride = 128; xout = g_cat0;      ostride = 128; }
    else if constexpr (LAYER == 3) { xin = g_cat0;      istride = 128; xout = g_cat1;      ostride = 96;  }
    else                           { xin = g_cat1;      istride = 96;  xout = g_h5;        ostride = 32;  }

    __shared__ __align__(16) float smem[SMAX + 8 * CI];
    float* Ys = smem;             // [8][KT]  (later overlaid by reduction buffer)
    float* Xs = smem + SMAX;      // [8][CI]

    int tid = threadIdx.x, lane = tid & 31, warp = tid >> 5;
    int nbase = blockIdx.x * 8;

    // Re-zero CSR scratch for the next run (g_count/g_fill dead after fill_kernel).
    if constexpr (LAYER == 0) {
        if (tid < 8) { g_count[nbase + tid] = 0; g_fill[nbase + tid] = 0; }
    }

    // ---- phase 1 ----
    {
        int n = nbase + warp;
        int s0 = g_rowptr[n], s1 = g_rowptr[n + 1];
        int deg = s1 - s0;
        int i_ch = lane % LPE;           // channel chunk (float4 index)
        int g    = lane / LPE;           // edge sub-slot within warp-iteration
        bool active = (g < EPW) && (4 * i_ch < CI);

        float acc[9][4];
#pragma unroll
        for (int k = 0; k < 9; ++k)
#pragma unroll
            for (int j = 0; j < 4; ++j) acc[k][j] = 0.f;

        int nit = (deg + EPW - 1) / EPW;

        float4 caB[2], cbB[2], ccB[2], xvB[2];
        bool   vB[2];
        auto LD = [&](int t, int b) {
            int s = s0 + t * EPW + g;
            bool ok = active && (s < s1);
            vB[b] = ok;
            if (ok) {
                int src = g_ssrc[s];
                const float4* cp = reinterpret_cast<const float4*>(g_scoef + (size_t)s * 12);
                caB[b] = cp[0]; cbB[b] = cp[1]; ccB[b] = cp[2];
                xvB[b] = *reinterpret_cast<const float4*>(xin + (size_t)src * istride + 4 * i_ch);
            }
        };
        if (nit > 0) LD(0, 0);
        if (nit > 1) LD(1, 1);
        for (int t = 0; t < nit; ++t) {
            int b = t & 1;
            float4 A = caB[b], Bc = cbB[b], C = ccB[b], X = xvB[b];
            bool ok = vB[b];
            if (t + 2 < nit) LD(t + 2, b);
            if (ok) {
                float c9[9] = {A.x, A.y, A.z, A.w, Bc.x, Bc.y, Bc.z, Bc.w, C.x};
#pragma unroll
                for (int k = 0; k < 9; ++k) {
                    acc[k][0] += c9[k] * X.x;
                    acc[k][1] += c9[k] * X.y;
                    acc[k][2] += c9[k] * X.z;
                    acc[k][3] += c9[k] * X.w;
                }
            }
        }

        // cross-group reduction (sum over edge sub-slots)
        if constexpr (EPW > 1) {
#pragma unroll
            for (int m = LPE; m < 32; m <<= 1)
#pragma unroll
                for (int k = 0; k < 9; ++k)
#pragma unroll
                    for (int j = 0; j < 4; ++j)
                        acc[k][j] += __shfl_xor_sync(0xffffffffu, acc[k][j], m);
        }

        float inv = 1.0f / (float)max(1, deg);
        if (g == 0 && 4 * i_ch < CI) {
#pragma unroll
            for (int k = 0; k < 9; ++k) {
                float4 yv = make_float4(acc[k][0] * inv, acc[k][1] * inv,
                                        acc[k][2] * inv, acc[k][3] * inv);
                *reinterpret_cast<float4*>(&Ys[warp * KT + k * CI + 4 * i_ch]) = yv;
            }
        }
        if (4 * lane < CI)
            *reinterpret_cast<float4*>(&Xs[warp * CI + 4 * lane]) =
                *reinterpret_cast<const float4*>(xin + (size_t)n * istride + 4 * lane);
    }
    __syncthreads();

    // ---- phase 2: warp-split-K GEMM (measured-best R6 form) ----
    if constexpr (CO == 64) {
        float2 acc2[8];
#pragma unroll
        for (int r = 0; r < 8; ++r) acc2[r] = make_float2(0.f, 0.f);

#pragma unroll 2
        for (int p4 = warp; p4 < KT / 4; p4 += 8) {
            int k = 4 * p4;
            float wA[4], wB[4];
#pragma unroll
            for (int i = 0; i < 4; ++i) {
                wA[i] = __ldg(W + (size_t)(k + i) * CO + lane);
                wB[i] = __ldg(W + (size_t)(k + i) * CO + lane + 32);
            }
#pragma unroll
            for (int r = 0; r < 8; ++r) {
                float4 y = *reinterpret_cast<const float4*>(&Ys[r * KT + k]);
                acc2[r] = ffma2(make_float2(y.x, y.x), make_float2(wA[0], wB[0]), acc2[r]);
                acc2[r] = ffma2(make_float2(y.y, y.y), make_float2(wA[1], wB[1]), acc2[r]);
                acc2[r] = ffma2(make_float2(y.z, y.z), make_float2(wA[2], wB[2]), acc2[r]);
                acc2[r] = ffma2(make_float2(y.w, y.w), make_float2(wA[3], wB[3]), acc2[r]);
            }
        }
#pragma unroll 2
        for (int p4 = warp; p4 < CI / 4; p4 += 8) {
            int k = 4 * p4;
            float wA[4], wB[4];
#pragma unroll
            for (int i = 0; i < 4; ++i) {
                wA[i] = __ldg(root + (size_t)(k + i) * CO + lane);
                wB[i] = __ldg(root + (size_t)(k + i) * CO + lane + 32);
            }
#pragma unroll
            for (int r = 0; r < 8; ++r) {
                float4 y = *reinterpret_cast<const float4*>(&Xs[r * CI + k]);
                acc2[r] = ffma2(make_float2(y.x, y.x), make_float2(wA[0], wB[0]), acc2[r]);
                acc2[r] = ffma2(make_float2(y.y, y.y), make_float2(wA[1], wB[1]), acc2[r]);
                acc2[r] = ffma2(make_float2(y.z, y.z), make_float2(wA[2], wB[2]), acc2[r]);
                acc2[r] = ffma2(make_float2(y.w, y.w), make_float2(wA[3], wB[3]), acc2[r]);
            }
        }
        __syncthreads();
        float* red = smem;   // [8 warps][8 rows][CO]
#pragma unroll
        for (int r = 0; r < 8; ++r) {
            red[(warp * 8 + r) * CO + lane]      = acc2[r].x;
            red[(warp * 8 + r) * CO + lane + 32] = acc2[r].y;
        }
        __syncthreads();
        int r = warp;
        float vA = __ldg(bias + lane), vB = __ldg(bias + lane + 32);
#pragma unroll
        for (int w = 0; w < 8; ++w) {
            vA += red[(w * 8 + r) * CO + lane];
            vB += red[(w * 8 + r) * CO + lane + 32];
        }
        vA = fminf(fmaxf(vA, 0.f), 6.f);
        vB = fminf(fmaxf(vB, 0.f), 6.f);
        xout[(size_t)(nbase + r) * ostride + lane]      = vA;
        xout[(size_t)(nbase + r) * ostride + lane + 32] = vB;
    } else {  // CO == 32
        float2 acc2[4];
#pragma unroll
        for (int j = 0; j < 4; ++j) acc2[j] = make_float2(0.f, 0.f);

#pragma unroll 2
        for (int p4 = warp; p4 < KT / 4; p4 += 8) {
            int k = 4 * p4;
            float w4[4];
#pragma unroll
            for (int i = 0; i < 4; ++i) w4[i] = __ldg(W + (size_t)(k + i) * CO + lane);
#pragma unroll
            for (int j = 0; j < 4; ++j) {
                float4 ya = *reinterpret_cast<const float4*>(&Ys[(2 * j) * KT + k]);
                float4 yb = *reinterpret_cast<const float4*>(&Ys[(2 * j + 1) * KT + k]);
                acc2[j] = ffma2(make_float2(ya.x, yb.x), make_float2(w4[0], w4[0]), acc2[j]);
                acc2[j] = ffma2(make_float2(ya.y, yb.y), make_float2(w4[1], w4[1]), acc2[j]);
                acc2[j] = ffma2(make_float2(ya.z, yb.z), make_float2(w4[2], w4[2]), acc2[j]);
                acc2[j] = ffma2(make_float2(ya.w, yb.w), make_float2(w4[3], w4[3]), acc2[j]);
            }
        }
#pragma unroll 2
        for (int p4 = warp; p4 < CI / 4; p4 += 8) {
            int k = 4 * p4;
            float w4[4];
#pragma unroll
            for (int i = 0; i < 4; ++i) w4[i] = __ldg(root + (size_t)(k + i) * CO + lane);
#pragma unroll
            for (int j = 0; j < 4; ++j) {
                float4 ya = *reinterpret_cast<const float4*>(&Xs[(2 * j) * CI + k]);
                float4 yb = *reinterpret_cast<const float4*>(&Xs[(2 * j + 1) * CI + k]);
                acc2[j] = ffma2(make_float2(ya.x, yb.x), make_float2(w4[0], w4[0]), acc2[j]);
                acc2[j] = ffma2(make_float2(ya.y, yb.y), make_float2(w4[1], w4[1]), acc2[j]);
                acc2[j] = ffma2(make_float2(ya.z, yb.z), make_float2(w4[2], w4[2]), acc2[j]);
                acc2[j] = ffma2(make_float2(ya.w, yb.w), make_float2(w4[3], w4[3]), acc2[j]);
            }
        }
        __syncthreads();
        float* red = smem;   // [8 warps][8 rows][CO]
#pragma unroll
        for (int j = 0; j < 4; ++j) {
            red[(warp * 8 + 2 * j) * CO + lane]     = acc2[j].x;
            red[(warp * 8 + 2 * j + 1) * CO + lane] = acc2[j].y;
        }
        __syncthreads();
        int r = warp;
        float v = __ldg(bias + lane);
#pragma unroll
        for (int w = 0; w < 8; ++w) v += red[(w * 8 + r) * CO + lane];
        v = fminf(fmaxf(v, 0.f), 6.f);
        xout[(size_t)(nbase + r) * ostride + lane] = v;
    }
}

// ---------------- lin1 split-K GEMM: [64,32768] x [32768,128] ----------------
__launch_bounds__(256)
__global__ void lin1_partial_kernel(const float* __restrict__ W) {
    __shared__ __align__(16) float As[64 * 32];
    __shared__ __align__(16) float Bs[32 * 128];
    int tid = threadIdx.x;
    int k0 = blockIdx.x * 128;
    int colg = tid & 31;
    int rowg = tid >> 5;
    float4 acc[8];
#pragma unroll
    for (int i = 0; i < 8; ++i) acc[i] = make_float4(0.f, 0.f, 0.f, 0.f);

    for (int ch = 0; ch < 4; ++ch) {
        int kb = k0 + ch * 32;
        for (int idx = tid; idx < 64 * 32; idx += 256) {
            int b = idx >> 5, kk = idx & 31;
            As[idx] = g_h5[(size_t)b * 32768 + kb + kk];
        }
        for (int idx = tid; idx < 32 * 128; idx += 256) {
            int kk = idx >> 7, c = idx & 127;
            Bs[idx] = W[(size_t)(kb + kk) * 128 + c];
        }
        __syncthreads();
        for (int kk = 0; kk < 32; ++kk) {
            float4 w = *reinterpret_cast<const float4*>(&Bs[kk * 128 + 4 * colg]);
#pragma unroll
            for (int i = 0; i < 8; ++i) {
                float a = As[(rowg + 8 * i) * 32 + kk];
                acc[i].x += a * w.x; acc[i].y += a * w.y;
                acc[i].z += a * w.z; acc[i].w += a * w.w;
            }
        }
        __syncthreads();
    }
#pragma unroll
    for (int i = 0; i < 8; ++i)
        *reinterpret_cast<float4*>(&g_part[(size_t)blockIdx.x * 8192 + (rowg + 8 * i) * 128 + 4 * colg]) = acc[i];
}

__global__ void lin2_kernel(const float* __restrict__ lin1b,
                            const float* __restrict__ lin2W, const float* __restrict__ lin2b,
                            float* __restrict__ out) {
    __shared__ float h[128];
    int b = blockIdx.x, c = threadIdx.x;
    float s = 0.f;
    for (int sp = 0; sp < 256; ++sp) s += g_part[(size_t)sp * 8192 + b * 128 + c];
    s += lin1b[c];
    h[c] = fmaxf(s, 0.f);
    __syncthreads();
    if (c < 3) {
        float o = lin2b[c];
#pragma unroll 4
        for (int i = 0; i < 128; ++i) o += h[i] * lin2W[i * 3 + c];
        out[b * 3 + c] = o;
    }
}

// ---------------- host ----------------
extern "C" void kernel_launch(void* const* d_in, const int* in_sizes, int n_in,
                              void* d_out, int out_size) {
    const float* x    = (const float*)d_in[0];
    const int*   ei   = (const int*)d_in[1];     // int32 (JAX x64 disabled)
    const float* pos  = (const float*)d_in[2];
    const float* enc0_W = (const float*)d_in[4],  *enc0_R = (const float*)d_in[5],  *enc0_b = (const float*)d_in[6];
    const float* enc1_W = (const float*)d_in[7],  *enc1_R = (const float*)d_in[8],  *enc1_b = (const float*)d_in[9];
    const float* enc2_W = (const float*)d_in[10], *enc2_R = (const float*)d_in[11], *enc2_b = (const float*)d_in[12];
    const float* dec0_W = (const float*)d_in[13], *dec0_R = (const float*)d_in[14], *dec0_b = (const float*)d_in[15];
    const float* dec1_W = (const float*)d_in[16], *dec1_R = (const float*)d_in[17], *dec1_b = (const float*)d_in[18];
    const float* lin1_W = (const float*)d_in[19], *lin1_b = (const float*)d_in[20];
    const float* lin2_W = (const float*)d_in[21], *lin2_b = (const float*)d_in[22];
    float* out = (float*)d_out;

    count_kernel<<<(N_EDGES + 255) / 256, 256>>>(ei);
    scan_kernel<<<1, 1024>>>();
    fill_kernel<<<(N_EDGES + 255) / 256, 256>>>(ei, pos);

    spline_conv_kernel<16, 32, 0><<<N_NODES / 8, 256>>>(x, enc0_W, enc0_R, enc0_b);
    spline_conv_kernel<32, 64, 1><<<N_NODES / 8, 256>>>(nullptr, enc1_W, enc1_R, enc1_b);
    spline_conv_kernel<64, 64, 2><<<N_NODES / 8, 256>>>(nullptr, enc2_W, enc2_R, enc2_b);
    spline_conv_kernel<128, 64, 3><<<N_NODES / 8, 256>>>(nullptr, dec0_W, dec0_R, dec0_b);
    spline_conv_kernel<96, 32, 4><<<N_NODES / 8, 256>>>(nullptr, dec1_W, dec1_R, dec1_b);

    lin1_partial_kernel<<<256, 256>>>(lin1_W);
    lin2_kernel<<<NGRAPH, 128>>>(lin1_b, lin2_W, lin2_b, out);
}